// round 14
// baseline (speedup 1.0000x reference)
#include <cuda_runtime.h>
#include <cuda_fp16.h>

#define NTHREADS 256
#define MAX_BLOCKS 8192

#define C_PER_SAMPLE 7.1624450756f
#define C_ENTROPY    5.6757541328f

// ---------------- fragment-ordered weight tables ----------------
// mma.m16n8k16 lane map: g = lane/4 (row), tg = lane%4 (col pair).
struct Tab {
    float4 l1f[32][16];    // per-lane layer1 (w0,w1,b,0); idx i=kc*4+e ->
                           // col c = 16*kc + 2*tg + (e&1) + 8*(e>>1)
    uint2  b2f[4][4][32];  // [nt][kc][lane]: B2 frag {pack(k0,k0+1),pack(k0+8,k0+9)} at n
    uint2  b3f[2][2][32];  // [nt2][kc2][lane]
    float  b2p[32];        // layer2 bias by n (pad 0)
    float  b3p[16];        // layer3 bias by n_out (pad 0)
};

__device__ Tab g_tab;
__device__ double g_partial[MAX_BLOCKS];
__device__ unsigned int g_ticket;   // zero-init; last block resets

__device__ __forceinline__ unsigned packh2(float a, float b)
{
    __half2 h = __floats2half2_rn(a, b);
    return *reinterpret_cast<unsigned*>(&h);
}

// ---------------------------------------------------------------------------
// Dense helpers for the block-diagonal fused net (device side, pack only).
// H cols c: net m=c/20, j=c%20 (c<60). H2 cols n: net n/10, unit n%10 (n<30).
// OUT cols: 0..3 mu(net0), 4..7 ld(net1), 8..13 off(net2), 14..15 pad.
__device__ float b2val(const float* const* W2, int c, int n)
{
    if (n >= 30 || c >= 60) return 0.0f;
    int mn = n / 10;
    if (c / 20 != mn) return 0.0f;
    int j = c - 20 * mn;
    return W2[mn][j * 10 + (n % 10)];
}
__device__ float b3val(const float* const* W3, int k, int nout)
{
    if (nout >= 14 || k >= 30) return 0.0f;
    int nm = (nout < 4) ? 0 : (nout < 8) ? 1 : 2;
    int o = nout - ((nm == 0) ? 0 : (nm == 1) ? 4 : 8);
    int OUT = (nm == 2) ? 6 : 4;
    if (k / 10 != nm) return 0.0f;
    return W3[nm][(k % 10) * OUT + o];
}

__global__ void pack_kernel(
    const float* mW1, const float* mb1, const float* mW2, const float* mb2,
    const float* mW3, const float* mb3,
    const float* dW1, const float* db1, const float* dW2, const float* db2,
    const float* dW3, const float* db3,
    const float* oW1, const float* ob1, const float* oW2, const float* ob2,
    const float* oW3, const float* ob3)
{
    const float* W1[3] = {mW1, dW1, oW1};
    const float* B1[3] = {mb1, db1, ob1};
    const float* W2[3] = {mW2, dW2, oW2};
    const float* B2[3] = {mb2, db2, ob2};
    const float* W3[3] = {mW3, dW3, oW3};
    const float* B3[3] = {mb3, db3, ob3};
    int t = threadIdx.x;

    for (int idx = t; idx < 512; idx += blockDim.x) {      // l1f
        int l = idx / 16, i = idx % 16;
        int tg = l % 4;
        int c = 16 * (i / 4) + 2 * tg + ((i % 4) & 1) + 8 * ((i % 4) >> 1);
        float4 v = make_float4(0.f, 0.f, 0.f, 0.f);
        if (c < 60) {
            int m = c / 20, j = c % 20;
            v = make_float4(W1[m][j], W1[m][20 + j], B1[m][j], 0.f);
        }
        g_tab.l1f[l][i] = v;
    }
    for (int idx = t; idx < 512; idx += blockDim.x) {      // b2f
        int nt = idx / 128, r = idx % 128, kc = r / 32, l = r % 32;
        int g = l / 4, tg = l % 4;
        int k0 = 16 * kc + 2 * tg, n = 8 * nt + g;
        g_tab.b2f[nt][kc][l] = make_uint2(
            packh2(b2val(W2, k0, n),     b2val(W2, k0 + 1, n)),
            packh2(b2val(W2, k0 + 8, n), b2val(W2, k0 + 9, n)));
    }
    for (int idx = t; idx < 128; idx += blockDim.x) {      // b3f
        int nt2 = idx / 64, r = idx % 64, kc2 = r / 32, l = r % 32;
        int g = l / 4, tg = l % 4;
        int k0 = 16 * kc2 + 2 * tg, n = 8 * nt2 + g;
        g_tab.b3f[nt2][kc2][l] = make_uint2(
            packh2(b3val(W3, k0, n),     b3val(W3, k0 + 1, n)),
            packh2(b3val(W3, k0 + 8, n), b3val(W3, k0 + 9, n)));
    }
    for (int n = t; n < 32; n += blockDim.x)
        g_tab.b2p[n] = (n < 30) ? B2[n / 10][n % 10] : 0.0f;
    for (int n = t; n < 16; n += blockDim.x) {
        float v = 0.0f;
        if (n < 14) {
            int nm = (n < 4) ? 0 : (n < 8) ? 1 : 2;
            int o = n - ((nm == 0) ? 0 : (nm == 1) ? 4 : 8);
            v = B3[nm][o];
        }
        g_tab.b3p[n] = v;
    }
}

// ---------------------------------------------------------------------------
__device__ __forceinline__ void mma16816(float* d, const unsigned* a,
                                         const uint2 b, const float* c)
{
    asm volatile(
        "mma.sync.aligned.m16n8k16.row.col.f32.f16.f16.f32 "
        "{%0,%1,%2,%3}, {%4,%5,%6,%7}, {%8,%9}, {%10,%11,%12,%13};"
        : "=f"(d[0]), "=f"(d[1]), "=f"(d[2]), "=f"(d[3])
        : "r"(a[0]), "r"(a[1]), "r"(a[2]), "r"(a[3]),
          "r"(b.x), "r"(b.y),
          "f"(c[0]), "f"(c[1]), "f"(c[2]), "f"(c[3]));
}

__device__ __forceinline__ float softplus_f(float x)
{
    return fmaxf(x, 0.0f) + __logf(1.0f + __expf(-fabsf(x)));
}

#define SMEM_STRIDE 17

// ---------------------------------------------------------------------------
__global__ void __launch_bounds__(NTHREADS, 4)
vi_kernel(const float* __restrict__ y, const float* __restrict__ zs, int N,
          float* __restrict__ out)
{
    __shared__ float smemF[NTHREADS * SMEM_STRIDE];   // [256 rows][17]
    __shared__ double sred[NTHREADS];
    __shared__ float wsum[NTHREADS / 32];
    __shared__ int sh_last;

    int tid = threadIdx.x;
    int warp = tid / 32, lane = tid % 32;
    int g = lane / 4, tg = lane % 4;
    int blockRow = blockIdx.x * NTHREADS;
    const float2* y2 = (const float2*)y;

    // ---------------- MLP phase: two m16 tiles per warp ----------------
#pragma unroll
    for (int t = 0; t < 2; t++) {
        int tileRow = blockRow + warp * 32 + t * 16;
        int r0 = tileRow + g;     if (r0 > N - 1) r0 = N - 1;
        int r1 = tileRow + g + 8; if (r1 > N - 1) r1 = N - 1;
        float2 yA = __ldg(&y2[r0]);
        float2 yB = __ldg(&y2[r1]);

        // layer1 directly into A-fragment registers
        unsigned a[4][4];
#pragma unroll
        for (int kc = 0; kc < 4; kc++) {
            float hA[4], hB[4];
#pragma unroll
            for (int e = 0; e < 4; e++) {
                float4 w = __ldg(&g_tab.l1f[lane][4 * kc + e]);
                hA[e] = fmaxf(fmaf(w.x, yA.x, fmaf(w.y, yA.y, w.z)), 0.0f);
                hB[e] = fmaxf(fmaf(w.x, yB.x, fmaf(w.y, yB.y, w.z)), 0.0f);
            }
            a[kc][0] = packh2(hA[0], hA[1]);
            a[kc][1] = packh2(hB[0], hB[1]);
            a[kc][2] = packh2(hA[2], hA[3]);
            a[kc][3] = packh2(hB[2], hB[3]);
        }

        // layer2: H[16x64] @ B2[64x32] -> H2, fp32 accum, bias init
        float h2[16];
#pragma unroll
        for (int nt = 0; nt < 4; nt++) {
            float c0b = __ldg(&g_tab.b2p[8 * nt + 2 * tg]);
            float c1b = __ldg(&g_tab.b2p[8 * nt + 2 * tg + 1]);
            float d[4] = {c0b, c1b, c0b, c1b};
#pragma unroll
            for (int kc = 0; kc < 4; kc++) {
                uint2 bb = __ldg(&g_tab.b2f[nt][kc][lane]);
                mma16816(d, a[kc], bb, d);
            }
            h2[4 * nt + 0] = fmaxf(d[0], 0.0f);
            h2[4 * nt + 1] = fmaxf(d[1], 0.0f);
            h2[4 * nt + 2] = fmaxf(d[2], 0.0f);
            h2[4 * nt + 3] = fmaxf(d[3], 0.0f);
        }

        // D->A chaining: relu'd D1 is already in A-fragment layout
        unsigned a2[2][4];
        a2[0][0] = packh2(h2[0],  h2[1]);
        a2[0][1] = packh2(h2[2],  h2[3]);
        a2[0][2] = packh2(h2[4],  h2[5]);
        a2[0][3] = packh2(h2[6],  h2[7]);
        a2[1][0] = packh2(h2[8],  h2[9]);
        a2[1][1] = packh2(h2[10], h2[11]);
        a2[1][2] = packh2(h2[12], h2[13]);
        a2[1][3] = packh2(h2[14], h2[15]);

        // layer3: H2[16x32] @ B3[32x16] -> outputs, store to smem
#pragma unroll
        for (int nt2 = 0; nt2 < 2; nt2++) {
            float c0b = __ldg(&g_tab.b3p[8 * nt2 + 2 * tg]);
            float c1b = __ldg(&g_tab.b3p[8 * nt2 + 2 * tg + 1]);
            float d[4] = {c0b, c1b, c0b, c1b};
#pragma unroll
            for (int kc2 = 0; kc2 < 2; kc2++) {
                uint2 bb = __ldg(&g_tab.b3f[nt2][kc2][lane]);
                mma16816(d, a2[kc2], bb, d);
            }
            int lr0 = warp * 32 + t * 16 + g;
            int lr1 = lr0 + 8;
            int n0 = 8 * nt2 + 2 * tg;
            smemF[lr0 * SMEM_STRIDE + n0]     = d[0];
            smemF[lr0 * SMEM_STRIDE + n0 + 1] = d[1];
            smemF[lr1 * SMEM_STRIDE + n0]     = d[2];
            smemF[lr1 * SMEM_STRIDE + n0 + 1] = d[3];
        }
    }
    __syncwarp();

    // ---------------- sample phase: 1 row per thread ----------------
    int n = blockRow + tid;
    float val = 0.0f;
    if (n < N) {
        const float* f = &smemF[tid * SMEM_STRIDE];
        float mu0 = f[0], mu1 = f[1], mu2 = f[2], mu3 = f[3];
        float d0 = softplus_f(f[4]);
        float d1 = softplus_f(f[5]);
        float d2 = softplus_f(f[6]);
        float d3 = softplus_f(f[7]);
        float o0 = f[8], o1 = f[9], o2 = f[10], o3 = f[11], o4 = f[12], o5 = f[13];

        float2 yv = __ldg(&y2[n]);
        float yx100 = yv.x * 100.0f;
        float yy100 = yv.y * 100.0f;

        const float4* zp = (const float4*)zs + (size_t)n * 8;
        float acc = 0.0f;
#pragma unroll
        for (int p = 0; p < 8; p++) {
            float4 z = __ldg(&zp[p]);
            float xi0 = fmaf(d0, z.x, mu0);
            float xi1 = fmaf(d1, z.y, fmaf(o0, z.x, mu1));
            float xi2 = fmaf(d2, z.z, fmaf(o2, z.y, fmaf(o1, z.x, mu2)));
            float xi3 = fmaf(d3, z.w, fmaf(o5, z.z, fmaf(o4, z.y, fmaf(o3, z.x, mu3))));

            float a2a = xi1 + xi2;
            float a3a = a2a + xi3;
            float s1, c1, s2, c2, s3, c3;
            __sincosf(xi1, &s1, &c1);
            __sincosf(a2a, &s2, &c2);
            __sincosf(a3a, &s3, &c3);

            float px = fmaf(0.5f, c1, fmaf(0.5f, c2, c3));
            float py = xi0 + fmaf(0.5f, s1, fmaf(0.5f, s2, s3));

            float rx = fmaf(-100.0f, px, yx100);
            float ry = fmaf(-100.0f, py, yy100);

            float s123 = fmaf(xi1, xi1, fmaf(xi2, xi2, xi3 * xi3));
            float tq = fmaf(xi0 * -8.0f, xi0, -2.0f * s123);
            float r2 = fmaf(rx, rx, ry * ry);
            acc += fmaf(-0.5f, r2, tq);
        }

        val = fmaf(acc, 0.125f, C_PER_SAMPLE) + C_ENTROPY +
              __logf(d0 * d1 * d2 * d3);
    }

    // ---- deterministic block reduction ----
#pragma unroll
    for (int o = 16; o > 0; o >>= 1)
        val += __shfl_down_sync(0xffffffffu, val, o);
    if ((tid & 31) == 0) wsum[tid >> 5] = val;
    __syncthreads();
    if (tid == 0) {
        double s = 0.0;
#pragma unroll
        for (int w = 0; w < NTHREADS / 32; w++) s += (double)wsum[w];
        g_partial[blockIdx.x] = s;
        __threadfence();
        unsigned t = atomicAdd(&g_ticket, 1u);
        sh_last = (t == gridDim.x - 1) ? 1 : 0;
    }
    __syncthreads();

    if (sh_last) {
        __threadfence();
        double s = 0.0;
        for (int i = tid; i < (int)gridDim.x; i += NTHREADS)
            s += __ldcg(&g_partial[i]);
        sred[tid] = s;
        __syncthreads();
#pragma unroll
        for (int st = NTHREADS / 2; st > 0; st >>= 1) {
            if (tid < st) sred[tid] += sred[tid + st];
            __syncthreads();
        }
        if (tid == 0) {
            out[0] = (float)(sred[0] / (double)N);
            __threadfence();
            g_ticket = 0;
        }
    }
}

// ---------------------------------------------------------------------------
extern "C" void kernel_launch(void* const* d_in, const int* in_sizes, int n_in,
                              void* d_out, int out_size)
{
    const float* y  = (const float*)d_in[0];
    const float* zs = (const float*)d_in[1];
    int N = in_sizes[0] / 2;
    int nblocks = (N + NTHREADS - 1) / NTHREADS;
    if (nblocks > MAX_BLOCKS) nblocks = MAX_BLOCKS;

    pack_kernel<<<1, 128>>>(
        (const float*)d_in[2],  (const float*)d_in[3],  (const float*)d_in[4],
        (const float*)d_in[5],  (const float*)d_in[6],  (const float*)d_in[7],
        (const float*)d_in[8],  (const float*)d_in[9],  (const float*)d_in[10],
        (const float*)d_in[11], (const float*)d_in[12], (const float*)d_in[13],
        (const float*)d_in[14], (const float*)d_in[15], (const float*)d_in[16],
        (const float*)d_in[17], (const float*)d_in[18], (const float*)d_in[19]);

    vi_kernel<<<nblocks, NTHREADS>>>(y, zs, N, (float*)d_out);
}

// round 15
// speedup vs baseline: 1.5376x; 1.5376x over previous
#include <cuda_runtime.h>
#include <cuda_fp16.h>

#define NTHREADS 256
#define MAX_BLOCKS 8192

#define C_PER_SAMPLE 7.1624450756f
#define C_ENTROPY    5.6757541328f

// ---------------- fragment-ordered weight tables (verified in R14) ----------
// mma.m16n8k16 lane map: g = lane/4 (row), tg = lane%4 (col pair).
struct Tab {
    float4 l1f[16][32];    // [i][lane] (lane-minor: conflict-free LDS.128)
                           // i=kc*4+e -> col c = 16*kc + 2*tg + (e&1) + 8*(e>>1)
    uint2  b2f[4][4][32];  // [nt][kc][lane]: {pack(k0,k0+1),pack(k0+8,k0+9)} at n
    uint2  b3f[2][2][32];  // [nt2][kc2][lane]
    float  b2p[32];        // layer2 bias by n (pad 0)
    float  b3p[16];        // layer3 bias by n_out (pad 0)
};
#define TAB_U4 (sizeof(Tab) / 16)

__device__ Tab g_tab;
__device__ double g_partial[MAX_BLOCKS];
__device__ unsigned int g_ticket;   // zero-init; last block resets

__device__ __forceinline__ unsigned packh2(float a, float b)
{
    __half2 h = __floats2half2_rn(a, b);
    return *reinterpret_cast<unsigned*>(&h);
}

// ---------------------------------------------------------------------------
// Block-diagonal fused net value helpers (pack side only).
__device__ float b2val(const float* const* W2, int c, int n)
{
    if (n >= 30 || c >= 60) return 0.0f;
    int mn = n / 10;
    if (c / 20 != mn) return 0.0f;
    int j = c - 20 * mn;
    return W2[mn][j * 10 + (n % 10)];
}
__device__ float b3val(const float* const* W3, int k, int nout)
{
    if (nout >= 14 || k >= 30) return 0.0f;
    int nm = (nout < 4) ? 0 : (nout < 8) ? 1 : 2;
    int o = nout - ((nm == 0) ? 0 : (nm == 1) ? 4 : 8);
    int OUT = (nm == 2) ? 6 : 4;
    if (k / 10 != nm) return 0.0f;
    return W3[nm][(k % 10) * OUT + o];
}

__global__ void pack_kernel(
    const float* mW1, const float* mb1, const float* mW2, const float* mb2,
    const float* mW3, const float* mb3,
    const float* dW1, const float* db1, const float* dW2, const float* db2,
    const float* dW3, const float* db3,
    const float* oW1, const float* ob1, const float* oW2, const float* ob2,
    const float* oW3, const float* ob3)
{
    const float* W1[3] = {mW1, dW1, oW1};
    const float* B1[3] = {mb1, db1, ob1};
    const float* W2[3] = {mW2, dW2, oW2};
    const float* B2[3] = {mb2, db2, ob2};
    const float* W3[3] = {mW3, dW3, oW3};
    const float* B3[3] = {mb3, db3, ob3};
    int t = threadIdx.x;

    for (int idx = t; idx < 512; idx += blockDim.x) {      // l1f [i][lane]
        int i = idx / 32, l = idx % 32;
        int tg = l % 4;
        int c = 16 * (i / 4) + 2 * tg + ((i % 4) & 1) + 8 * ((i % 4) >> 1);
        float4 v = make_float4(0.f, 0.f, 0.f, 0.f);
        if (c < 60) {
            int m = c / 20, j = c % 20;
            v = make_float4(W1[m][j], W1[m][20 + j], B1[m][j], 0.f);
        }
        g_tab.l1f[i][l] = v;
    }
    for (int idx = t; idx < 512; idx += blockDim.x) {      // b2f
        int nt = idx / 128, r = idx % 128, kc = r / 32, l = r % 32;
        int g = l / 4, tg = l % 4;
        int k0 = 16 * kc + 2 * tg, n = 8 * nt + g;
        g_tab.b2f[nt][kc][l] = make_uint2(
            packh2(b2val(W2, k0, n),     b2val(W2, k0 + 1, n)),
            packh2(b2val(W2, k0 + 8, n), b2val(W2, k0 + 9, n)));
    }
    for (int idx = t; idx < 128; idx += blockDim.x) {      // b3f
        int nt2 = idx / 64, r = idx % 64, kc2 = r / 32, l = r % 32;
        int g = l / 4, tg = l % 4;
        int k0 = 16 * kc2 + 2 * tg, n = 8 * nt2 + g;
        g_tab.b3f[nt2][kc2][l] = make_uint2(
            packh2(b3val(W3, k0, n),     b3val(W3, k0 + 1, n)),
            packh2(b3val(W3, k0 + 8, n), b3val(W3, k0 + 9, n)));
    }
    for (int n = t; n < 32; n += blockDim.x)
        g_tab.b2p[n] = (n < 30) ? B2[n / 10][n % 10] : 0.0f;
    for (int n = t; n < 16; n += blockDim.x) {
        float v = 0.0f;
        if (n < 14) {
            int nm = (n < 4) ? 0 : (n < 8) ? 1 : 2;
            int o = n - ((nm == 0) ? 0 : (nm == 1) ? 4 : 8);
            v = B3[nm][o];
        }
        g_tab.b3p[n] = v;
    }
}

// ---------------------------------------------------------------------------
__device__ __forceinline__ void mma16816(float* d, const unsigned* a,
                                         const uint2 b, const float* c)
{
    asm volatile(
        "mma.sync.aligned.m16n8k16.row.col.f32.f16.f16.f32 "
        "{%0,%1,%2,%3}, {%4,%5,%6,%7}, {%8,%9}, {%10,%11,%12,%13};"
        : "=f"(d[0]), "=f"(d[1]), "=f"(d[2]), "=f"(d[3])
        : "r"(a[0]), "r"(a[1]), "r"(a[2]), "r"(a[3]),
          "r"(b.x), "r"(b.y),
          "f"(c[0]), "f"(c[1]), "f"(c[2]), "f"(c[3]));
}

__device__ __forceinline__ float softplus_f(float x)
{
    return fmaxf(x, 0.0f) + __logf(1.0f + __expf(-fabsf(x)));
}

#define SMEM_STRIDE 17

// ---------------------------------------------------------------------------
__global__ void __launch_bounds__(NTHREADS, 4)
vi_kernel(const float* __restrict__ y, const float* __restrict__ zs, int N,
          float* __restrict__ out)
{
    __shared__ Tab s_tab;                              // 13.5 KB
    __shared__ float smemF[NTHREADS * SMEM_STRIDE];    // 17.4 KB
    __shared__ double sred[NTHREADS];
    __shared__ float wsum[NTHREADS / 32];
    __shared__ int sh_last;

    int tid = threadIdx.x;
    // Stage fragment tables: uniform broadcast global reads, ~3.4/thread.
    {
        const uint4* src = (const uint4*)&g_tab;
        uint4* dst = (uint4*)&s_tab;
        for (int i = tid; i < (int)TAB_U4; i += NTHREADS)
            dst[i] = __ldg(&src[i]);
    }
    __syncthreads();

    int warp = tid / 32, lane = tid % 32;
    int g = lane / 4, tg = lane % 4;
    int blockRow = blockIdx.x * NTHREADS;
    const float2* y2 = (const float2*)y;

    // ---------------- MLP phase: two m16 tiles per warp ----------------
#pragma unroll
    for (int t = 0; t < 2; t++) {
        int tileRow = blockRow + warp * 32 + t * 16;
        int r0 = tileRow + g;     if (r0 > N - 1) r0 = N - 1;
        int r1 = tileRow + g + 8; if (r1 > N - 1) r1 = N - 1;
        float2 yA = __ldg(&y2[r0]);
        float2 yB = __ldg(&y2[r1]);

        // layer1 directly into A-fragment registers (weights from smem)
        unsigned a[4][4];
#pragma unroll
        for (int kc = 0; kc < 4; kc++) {
            float hA[4], hB[4];
#pragma unroll
            for (int e = 0; e < 4; e++) {
                float4 w = s_tab.l1f[4 * kc + e][lane];
                hA[e] = fmaxf(fmaf(w.x, yA.x, fmaf(w.y, yA.y, w.z)), 0.0f);
                hB[e] = fmaxf(fmaf(w.x, yB.x, fmaf(w.y, yB.y, w.z)), 0.0f);
            }
            a[kc][0] = packh2(hA[0], hA[1]);
            a[kc][1] = packh2(hB[0], hB[1]);
            a[kc][2] = packh2(hA[2], hA[3]);
            a[kc][3] = packh2(hB[2], hB[3]);
        }

        // layer2: H[16x64] @ B2[64x32], fp32 accum, bias init
        float h2[16];
#pragma unroll
        for (int nt = 0; nt < 4; nt++) {
            float c0b = s_tab.b2p[8 * nt + 2 * tg];
            float c1b = s_tab.b2p[8 * nt + 2 * tg + 1];
            float d[4] = {c0b, c1b, c0b, c1b};
#pragma unroll
            for (int kc = 0; kc < 4; kc++) {
                uint2 bb = s_tab.b2f[nt][kc][lane];
                mma16816(d, a[kc], bb, d);
            }
            h2[4 * nt + 0] = fmaxf(d[0], 0.0f);
            h2[4 * nt + 1] = fmaxf(d[1], 0.0f);
            h2[4 * nt + 2] = fmaxf(d[2], 0.0f);
            h2[4 * nt + 3] = fmaxf(d[3], 0.0f);
        }

        // D->A chaining: relu'd D1 already in A-fragment layout
        unsigned a2[2][4];
        a2[0][0] = packh2(h2[0],  h2[1]);
        a2[0][1] = packh2(h2[2],  h2[3]);
        a2[0][2] = packh2(h2[4],  h2[5]);
        a2[0][3] = packh2(h2[6],  h2[7]);
        a2[1][0] = packh2(h2[8],  h2[9]);
        a2[1][1] = packh2(h2[10], h2[11]);
        a2[1][2] = packh2(h2[12], h2[13]);
        a2[1][3] = packh2(h2[14], h2[15]);

        // layer3: H2[16x32] @ B3[32x16] -> outputs to smem
#pragma unroll
        for (int nt2 = 0; nt2 < 2; nt2++) {
            float c0b = s_tab.b3p[8 * nt2 + 2 * tg];
            float c1b = s_tab.b3p[8 * nt2 + 2 * tg + 1];
            float d[4] = {c0b, c1b, c0b, c1b};
#pragma unroll
            for (int kc2 = 0; kc2 < 2; kc2++) {
                uint2 bb = s_tab.b3f[nt2][kc2][lane];
                mma16816(d, a2[kc2], bb, d);
            }
            int lr0 = warp * 32 + t * 16 + g;
            int lr1 = lr0 + 8;
            int n0 = 8 * nt2 + 2 * tg;
            smemF[lr0 * SMEM_STRIDE + n0]     = d[0];
            smemF[lr0 * SMEM_STRIDE + n0 + 1] = d[1];
            smemF[lr1 * SMEM_STRIDE + n0]     = d[2];
            smemF[lr1 * SMEM_STRIDE + n0 + 1] = d[3];
        }
    }
    __syncwarp();   // sample phase reads only rows written by this warp

    // ---------------- sample phase: 1 row per thread ----------------
    int n = blockRow + tid;
    float val = 0.0f;
    if (n < N) {
        const float* f = &smemF[tid * SMEM_STRIDE];
        float mu0 = f[0], mu1 = f[1], mu2 = f[2], mu3 = f[3];
        float d0 = softplus_f(f[4]);
        float d1 = softplus_f(f[5]);
        float d2 = softplus_f(f[6]);
        float d3 = softplus_f(f[7]);
        float o0 = f[8], o1 = f[9], o2 = f[10], o3 = f[11], o4 = f[12], o5 = f[13];

        float2 yv = __ldg(&y2[n]);
        float yx100 = yv.x * 100.0f;
        float yy100 = yv.y * 100.0f;

        const float4* zp = (const float4*)zs + (size_t)n * 8;
        float acc = 0.0f;
#pragma unroll
        for (int p = 0; p < 8; p++) {
            float4 z = __ldg(&zp[p]);
            float xi0 = fmaf(d0, z.x, mu0);
            float xi1 = fmaf(d1, z.y, fmaf(o0, z.x, mu1));
            float xi2 = fmaf(d2, z.z, fmaf(o2, z.y, fmaf(o1, z.x, mu2)));
            float xi3 = fmaf(d3, z.w, fmaf(o5, z.z, fmaf(o4, z.y, fmaf(o3, z.x, mu3))));

            float a2a = xi1 + xi2;
            float a3a = a2a + xi3;
            float s1, c1, s2, c2, s3, c3;
            __sincosf(xi1, &s1, &c1);
            __sincosf(a2a, &s2, &c2);
            __sincosf(a3a, &s3, &c3);

            float px = fmaf(0.5f, c1, fmaf(0.5f, c2, c3));
            float py = xi0 + fmaf(0.5f, s1, fmaf(0.5f, s2, s3));

            float rx = fmaf(-100.0f, px, yx100);
            float ry = fmaf(-100.0f, py, yy100);

            float s123 = fmaf(xi1, xi1, fmaf(xi2, xi2, xi3 * xi3));
            float tq = fmaf(xi0 * -8.0f, xi0, -2.0f * s123);
            float r2 = fmaf(rx, rx, ry * ry);
            acc += fmaf(-0.5f, r2, tq);
        }

        val = fmaf(acc, 0.125f, C_PER_SAMPLE) + C_ENTROPY +
              __logf(d0 * d1 * d2 * d3);
    }

    // ---- deterministic block reduction ----
#pragma unroll
    for (int o = 16; o > 0; o >>= 1)
        val += __shfl_down_sync(0xffffffffu, val, o);
    if ((tid & 31) == 0) wsum[tid >> 5] = val;
    __syncthreads();
    if (tid == 0) {
        double s = 0.0;
#pragma unroll
        for (int w = 0; w < NTHREADS / 32; w++) s += (double)wsum[w];
        g_partial[blockIdx.x] = s;
        __threadfence();
        unsigned t = atomicAdd(&g_ticket, 1u);
        sh_last = (t == gridDim.x - 1) ? 1 : 0;
    }
    __syncthreads();

    if (sh_last) {
        __threadfence();
        double s = 0.0;
        for (int i = tid; i < (int)gridDim.x; i += NTHREADS)
            s += __ldcg(&g_partial[i]);
        sred[tid] = s;
        __syncthreads();
#pragma unroll
        for (int st = NTHREADS / 2; st > 0; st >>= 1) {
            if (tid < st) sred[tid] += sred[tid + st];
            __syncthreads();
        }
        if (tid == 0) {
            out[0] = (float)(sred[0] / (double)N);
            __threadfence();
            g_ticket = 0;
        }
    }
}

// ---------------------------------------------------------------------------
extern "C" void kernel_launch(void* const* d_in, const int* in_sizes, int n_in,
                              void* d_out, int out_size)
{
    const float* y  = (const float*)d_in[0];
    const float* zs = (const float*)d_in[1];
    int N = in_sizes[0] / 2;
    int nblocks = (N + NTHREADS - 1) / NTHREADS;
    if (nblocks > MAX_BLOCKS) nblocks = MAX_BLOCKS;

    pack_kernel<<<1, 128>>>(
        (const float*)d_in[2],  (const float*)d_in[3],  (const float*)d_in[4],
        (const float*)d_in[5],  (const float*)d_in[6],  (const float*)d_in[7],
        (const float*)d_in[8],  (const float*)d_in[9],  (const float*)d_in[10],
        (const float*)d_in[11], (const float*)d_in[12], (const float*)d_in[13],
        (const float*)d_in[14], (const float*)d_in[15], (const float*)d_in[16],
        (const float*)d_in[17], (const float*)d_in[18], (const float*)d_in[19]);

    vi_kernel<<<nblocks, NTHREADS>>>(y, zs, N, (float*)d_out);
}

// round 16
// speedup vs baseline: 1.7449x; 1.1349x over previous
#include <cuda_runtime.h>
#include <cuda_fp16.h>

#define NTHREADS 256
#define MAX_BLOCKS 8192

#define C_PER_SAMPLE 7.1624450756f
#define C_ENTROPY    5.6757541328f

// ---------------- fragment-ordered weight tables ----------------
// mma.m16n8k16 lane map: g = lane/4 (row), tg = lane%4 (col pair).
// Fused block-diagonal net: H cols c -> net m=c/20, unit j=c%20 (c<60).
// H2 cols n -> net n/10, unit n%10 (n<30). OUT cols: 0..3 mu, 4..7 ld,
// 8..13 off, 14..15 pad.
struct Tab {
    uint2 b1f[8][32];      // layer1 B-frags (bias folded via const-1 k-col)
    uint2 b2f[4][4][32];   // [nt][kc][lane]
    uint2 b3f[2][2][32];   // [nt2][kc2][lane]
    float b2p[32];         // layer2 bias by n (pad 0)
    float b3p[16];         // layer3 bias by n_out (pad 0)
};
#define TAB_U4 (sizeof(Tab) / 16)

__device__ Tab g_tab;
__device__ double g_partial[MAX_BLOCKS];
__device__ unsigned int g_ticket;   // zero-init; last block resets

__device__ __forceinline__ unsigned packh2(float a, float b)
{
    __half2 h = __floats2half2_rn(a, b);
    return *reinterpret_cast<unsigned*>(&h);
}

// ---------------------------------------------------------------------------
__device__ float b1val(const float* const* W1, const float* const* B1,
                       int k, int c)
{
    if (c >= 60) return 0.0f;
    int m = c / 20, j = c % 20;
    if (k == 0) return W1[m][j];
    if (k == 1) return W1[m][20 + j];
    if (k == 2) return B1[m][j];
    return 0.0f;
}
__device__ float b2val(const float* const* W2, int c, int n)
{
    if (n >= 30 || c >= 60) return 0.0f;
    int mn = n / 10;
    if (c / 20 != mn) return 0.0f;
    int j = c - 20 * mn;
    return W2[mn][j * 10 + (n % 10)];
}
__device__ float b3val(const float* const* W3, int k, int nout)
{
    if (nout >= 14 || k >= 30) return 0.0f;
    int nm = (nout < 4) ? 0 : (nout < 8) ? 1 : 2;
    int o = nout - ((nm == 0) ? 0 : (nm == 1) ? 4 : 8);
    int OUT = (nm == 2) ? 6 : 4;
    if (k / 10 != nm) return 0.0f;
    return W3[nm][(k % 10) * OUT + o];
}

__global__ void pack_kernel(
    const float* mW1, const float* mb1, const float* mW2, const float* mb2,
    const float* mW3, const float* mb3,
    const float* dW1, const float* db1, const float* dW2, const float* db2,
    const float* dW3, const float* db3,
    const float* oW1, const float* ob1, const float* oW2, const float* ob2,
    const float* oW3, const float* ob3)
{
    const float* W1[3] = {mW1, dW1, oW1};
    const float* B1[3] = {mb1, db1, ob1};
    const float* W2[3] = {mW2, dW2, oW2};
    const float* B2[3] = {mb2, db2, ob2};
    const float* W3[3] = {mW3, dW3, oW3};
    const float* B3[3] = {mb3, db3, ob3};
    int t = threadIdx.x;

    for (int idx = t; idx < 256; idx += blockDim.x) {      // b1f
        int nt = idx / 32, l = idx % 32;
        int g = l / 4, tg = l % 4;
        int n = 8 * nt + g, k0 = 2 * tg;
        g_tab.b1f[nt][l] = make_uint2(
            packh2(b1val(W1, B1, k0, n), b1val(W1, B1, k0 + 1, n)),
            0u);                                           // k>=8 rows all zero
    }
    for (int idx = t; idx < 512; idx += blockDim.x) {      // b2f
        int nt = idx / 128, r = idx % 128, kc = r / 32, l = r % 32;
        int g = l / 4, tg = l % 4;
        int k0 = 16 * kc + 2 * tg, n = 8 * nt + g;
        g_tab.b2f[nt][kc][l] = make_uint2(
            packh2(b2val(W2, k0, n),     b2val(W2, k0 + 1, n)),
            packh2(b2val(W2, k0 + 8, n), b2val(W2, k0 + 9, n)));
    }
    for (int idx = t; idx < 128; idx += blockDim.x) {      // b3f
        int nt2 = idx / 64, r = idx % 64, kc2 = r / 32, l = r % 32;
        int g = l / 4, tg = l % 4;
        int k0 = 16 * kc2 + 2 * tg, n = 8 * nt2 + g;
        g_tab.b3f[nt2][kc2][l] = make_uint2(
            packh2(b3val(W3, k0, n),     b3val(W3, k0 + 1, n)),
            packh2(b3val(W3, k0 + 8, n), b3val(W3, k0 + 9, n)));
    }
    for (int n = t; n < 32; n += blockDim.x)
        g_tab.b2p[n] = (n < 30) ? B2[n / 10][n % 10] : 0.0f;
    for (int n = t; n < 16; n += blockDim.x) {
        float v = 0.0f;
        if (n < 14) {
            int nm = (n < 4) ? 0 : (n < 8) ? 1 : 2;
            int o = n - ((nm == 0) ? 0 : (nm == 1) ? 4 : 8);
            v = B3[nm][o];
        }
        g_tab.b3p[n] = v;
    }
}

// ---------------------------------------------------------------------------
__device__ __forceinline__ void mma16816(float* d, const unsigned* a,
                                         const uint2 b, const float* c)
{
    asm volatile(
        "mma.sync.aligned.m16n8k16.row.col.f32.f16.f16.f32 "
        "{%0,%1,%2,%3}, {%4,%5,%6,%7}, {%8,%9}, {%10,%11,%12,%13};"
        : "=f"(d[0]), "=f"(d[1]), "=f"(d[2]), "=f"(d[3])
        : "r"(a[0]), "r"(a[1]), "r"(a[2]), "r"(a[3]),
          "r"(b.x), "r"(b.y),
          "f"(c[0]), "f"(c[1]), "f"(c[2]), "f"(c[3]));
}

__device__ __forceinline__ float softplus_f(float x)
{
    return fmaxf(x, 0.0f) + __logf(1.0f + __expf(-fabsf(x)));
}

#define SMEM_STRIDE 17

// ---------------------------------------------------------------------------
__global__ void __launch_bounds__(NTHREADS, 5)
vi_kernel(const float* __restrict__ y, const float* __restrict__ zs, int N,
          float* __restrict__ out)
{
    __shared__ Tab s_tab;                              // ~7.4 KB
    __shared__ float smemF[NTHREADS * SMEM_STRIDE];    // 17.4 KB
    __shared__ float wsum[NTHREADS / 32];
    __shared__ int sh_last;

    int tid = threadIdx.x;
    {
        const uint4* src = (const uint4*)&g_tab;
        uint4* dst = (uint4*)&s_tab;
        for (int i = tid; i < (int)TAB_U4; i += NTHREADS)
            dst[i] = __ldg(&src[i]);
    }
    __syncthreads();

    int warp = tid / 32, lane = tid % 32;
    int g = lane / 4, tg = lane % 4;
    int blockRow = blockIdx.x * NTHREADS;
    const float2* y2 = (const float2*)y;

    // ---------------- MLP phase: two m16 tiles per warp ----------------
#pragma unroll
    for (int t = 0; t < 2; t++) {
        int tileRow = blockRow + warp * 32 + t * 16;
        int r0 = tileRow + g;     if (r0 > N - 1) r0 = N - 1;
        int r1 = tileRow + g + 8; if (r1 > N - 1) r1 = N - 1;
        float2 yA = __ldg(&y2[r0]);
        float2 yB = __ldg(&y2[r1]);

        // Y A-fragment: cols 0=y0, 1=y1, 2=1, rest 0
        unsigned ya[4];
        ya[0] = (tg == 0) ? packh2(yA.x, yA.y) : (tg == 1) ? 0x00003C00u : 0u;
        ya[1] = (tg == 0) ? packh2(yB.x, yB.y) : (tg == 1) ? 0x00003C00u : 0u;
        ya[2] = 0u;
        ya[3] = 0u;

        // layer1 via MMA: Y[16x16] @ B1'[16x64]; bias folded (const-1 col).
        // D-tiles 2kc,2kc+1 chain into layer2 A-frag kc after relu+pack.
        unsigned a[4][4];
#pragma unroll
        for (int kc = 0; kc < 4; kc++) {
            float d0[4] = {0.f, 0.f, 0.f, 0.f};
            float d1[4] = {0.f, 0.f, 0.f, 0.f};
            mma16816(d0, ya, s_tab.b1f[2 * kc][lane], d0);
            mma16816(d1, ya, s_tab.b1f[2 * kc + 1][lane], d1);
            a[kc][0] = packh2(fmaxf(d0[0], 0.f), fmaxf(d0[1], 0.f));
            a[kc][1] = packh2(fmaxf(d0[2], 0.f), fmaxf(d0[3], 0.f));
            a[kc][2] = packh2(fmaxf(d1[0], 0.f), fmaxf(d1[1], 0.f));
            a[kc][3] = packh2(fmaxf(d1[2], 0.f), fmaxf(d1[3], 0.f));
        }

        // layer2: H[16x64] @ B2[64x32], fp32 accum, bias init
        float h2[16];
#pragma unroll
        for (int nt = 0; nt < 4; nt++) {
            float c0b = s_tab.b2p[8 * nt + 2 * tg];
            float c1b = s_tab.b2p[8 * nt + 2 * tg + 1];
            float d[4] = {c0b, c1b, c0b, c1b};
#pragma unroll
            for (int kc = 0; kc < 4; kc++)
                mma16816(d, a[kc], s_tab.b2f[nt][kc][lane], d);
            h2[4 * nt + 0] = fmaxf(d[0], 0.0f);
            h2[4 * nt + 1] = fmaxf(d[1], 0.0f);
            h2[4 * nt + 2] = fmaxf(d[2], 0.0f);
            h2[4 * nt + 3] = fmaxf(d[3], 0.0f);
        }

        unsigned a2[2][4];
        a2[0][0] = packh2(h2[0],  h2[1]);
        a2[0][1] = packh2(h2[2],  h2[3]);
        a2[0][2] = packh2(h2[4],  h2[5]);
        a2[0][3] = packh2(h2[6],  h2[7]);
        a2[1][0] = packh2(h2[8],  h2[9]);
        a2[1][1] = packh2(h2[10], h2[11]);
        a2[1][2] = packh2(h2[12], h2[13]);
        a2[1][3] = packh2(h2[14], h2[15]);

        // layer3: H2[16x32] @ B3[32x16] -> outputs to smem
#pragma unroll
        for (int nt2 = 0; nt2 < 2; nt2++) {
            float c0b = s_tab.b3p[8 * nt2 + 2 * tg];
            float c1b = s_tab.b3p[8 * nt2 + 2 * tg + 1];
            float d[4] = {c0b, c1b, c0b, c1b};
#pragma unroll
            for (int kc2 = 0; kc2 < 2; kc2++)
                mma16816(d, a2[kc2], s_tab.b3f[nt2][kc2][lane], d);
            int lr0 = warp * 32 + t * 16 + g;
            int lr1 = lr0 + 8;
            int n0 = 8 * nt2 + 2 * tg;
            smemF[lr0 * SMEM_STRIDE + n0]     = d[0];
            smemF[lr0 * SMEM_STRIDE + n0 + 1] = d[1];
            smemF[lr1 * SMEM_STRIDE + n0]     = d[2];
            smemF[lr1 * SMEM_STRIDE + n0 + 1] = d[3];
        }
    }
    __syncwarp();   // sample phase reads only rows written by this warp

    // ---------------- sample phase: 1 row per thread ----------------
    int n = blockRow + tid;
    float val = 0.0f;
    if (n < N) {
        const float* f = &smemF[tid * SMEM_STRIDE];
        float mu0 = f[0], mu1 = f[1], mu2 = f[2], mu3 = f[3];
        float d0 = softplus_f(f[4]);
        float d1 = softplus_f(f[5]);
        float d2 = softplus_f(f[6]);
        float d3 = softplus_f(f[7]);
        float o0 = f[8], o1 = f[9], o2 = f[10], o3 = f[11], o4 = f[12], o5 = f[13];

        float2 yv = __ldg(&y2[n]);
        float yx100 = yv.x * 100.0f;
        float yy100 = yv.y * 100.0f;

        const float4* zp = (const float4*)zs + (size_t)n * 8;
        float acc = 0.0f;
#pragma unroll
        for (int p = 0; p < 8; p++) {
            float4 z = __ldg(&zp[p]);
            float xi0 = fmaf(d0, z.x, mu0);
            float xi1 = fmaf(d1, z.y, fmaf(o0, z.x, mu1));
            float xi2 = fmaf(d2, z.z, fmaf(o2, z.y, fmaf(o1, z.x, mu2)));
            float xi3 = fmaf(d3, z.w, fmaf(o5, z.z, fmaf(o4, z.y, fmaf(o3, z.x, mu3))));

            float a2a = xi1 + xi2;
            float a3a = a2a + xi3;
            float s1, c1, s2, c2, s3, c3;
            __sincosf(xi1, &s1, &c1);
            __sincosf(a2a, &s2, &c2);
            __sincosf(a3a, &s3, &c3);

            float px = fmaf(0.5f, c1, fmaf(0.5f, c2, c3));
            float py = xi0 + fmaf(0.5f, s1, fmaf(0.5f, s2, s3));

            float rx = fmaf(-100.0f, px, yx100);
            float ry = fmaf(-100.0f, py, yy100);

            float s123 = fmaf(xi1, xi1, fmaf(xi2, xi2, xi3 * xi3));
            float tq = fmaf(xi0 * -8.0f, xi0, -2.0f * s123);
            float r2 = fmaf(rx, rx, ry * ry);
            acc += fmaf(-0.5f, r2, tq);
        }

        val = fmaf(acc, 0.125f, C_PER_SAMPLE) + C_ENTROPY +
              __logf(d0 * d1 * d2 * d3);
    }

    // ---- deterministic block reduction ----
#pragma unroll
    for (int o = 16; o > 0; o >>= 1)
        val += __shfl_down_sync(0xffffffffu, val, o);
    if ((tid & 31) == 0) wsum[tid >> 5] = val;
    __syncthreads();
    if (tid == 0) {
        double s = 0.0;
#pragma unroll
        for (int w = 0; w < NTHREADS / 32; w++) s += (double)wsum[w];
        g_partial[blockIdx.x] = s;
        __threadfence();
        unsigned t = atomicAdd(&g_ticket, 1u);
        sh_last = (t == gridDim.x - 1) ? 1 : 0;
    }
    __syncthreads();

    if (sh_last) {
        __threadfence();
        double s = 0.0;
        for (int i = tid; i < (int)gridDim.x; i += NTHREADS)
            s += __ldcg(&g_partial[i]);
        // reuse smemF as the double-reduction scratch
        double* sred = (double*)smemF;
        sred[tid] = s;
        __syncthreads();
#pragma unroll
        for (int st = NTHREADS / 2; st > 0; st >>= 1) {
            if (tid < st) sred[tid] += sred[tid + st];
            __syncthreads();
        }
        if (tid == 0) {
            out[0] = (float)(sred[0] / (double)N);
            __threadfence();
            g_ticket = 0;
        }
    }
}

// ---------------------------------------------------------------------------
extern "C" void kernel_launch(void* const* d_in, const int* in_sizes, int n_in,
                              void* d_out, int out_size)
{
    const float* y  = (const float*)d_in[0];
    const float* zs = (const float*)d_in[1];
    int N = in_sizes[0] / 2;
    int nblocks = (N + NTHREADS - 1) / NTHREADS;
    if (nblocks > MAX_BLOCKS) nblocks = MAX_BLOCKS;

    pack_kernel<<<1, 128>>>(
        (const float*)d_in[2],  (const float*)d_in[3],  (const float*)d_in[4],
        (const float*)d_in[5],  (const float*)d_in[6],  (const float*)d_in[7],
        (const float*)d_in[8],  (const float*)d_in[9],  (const float*)d_in[10],
        (const float*)d_in[11], (const float*)d_in[12], (const float*)d_in[13],
        (const float*)d_in[14], (const float*)d_in[15], (const float*)d_in[16],
        (const float*)d_in[17], (const float*)d_in[18], (const float*)d_in[19]);

    vi_kernel<<<nblocks, NTHREADS>>>(y, zs, N, (float*)d_out);
}

// round 17
// speedup vs baseline: 2.1233x; 1.2168x over previous
#include <cuda_runtime.h>
#include <cuda_fp16.h>

#define NTHREADS 256
#define MAX_BLOCKS 8192

#define C_PER_SAMPLE 7.1624450756f
#define C_ENTROPY    5.6757541328f

// ---------------- fragment-ordered weight tables (verified R14-R16) --------
struct Tab {
    uint2 b1f[8][32];      // layer1 B-frags (bias folded via const-1 k-col)
    uint2 b2f[4][4][32];   // [nt][kc][lane]
    uint2 b3f[2][2][32];   // [nt2][kc2][lane]
    float b2p[32];
    float b3p[16];
};
#define TAB_U4 (sizeof(Tab) / 16)

__device__ Tab g_tab;
__device__ double g_partial[MAX_BLOCKS];
__device__ unsigned int g_ticket;

__device__ __forceinline__ unsigned packh2(float a, float b)
{
    __half2 h = __floats2half2_rn(a, b);
    return *reinterpret_cast<unsigned*>(&h);
}

// ---------------------------------------------------------------------------
__device__ float b1val(const float* const* W1, const float* const* B1,
                       int k, int c)
{
    if (c >= 60) return 0.0f;
    int m = c / 20, j = c % 20;
    if (k == 0) return W1[m][j];
    if (k == 1) return W1[m][20 + j];
    if (k == 2) return B1[m][j];
    return 0.0f;
}
__device__ float b2val(const float* const* W2, int c, int n)
{
    if (n >= 30 || c >= 60) return 0.0f;
    int mn = n / 10;
    if (c / 20 != mn) return 0.0f;
    int j = c - 20 * mn;
    return W2[mn][j * 10 + (n % 10)];
}
__device__ float b3val(const float* const* W3, int k, int nout)
{
    if (nout >= 14 || k >= 30) return 0.0f;
    int nm = (nout < 4) ? 0 : (nout < 8) ? 1 : 2;
    int o = nout - ((nm == 0) ? 0 : (nm == 1) ? 4 : 8);
    int OUT = (nm == 2) ? 6 : 4;
    if (k / 10 != nm) return 0.0f;
    return W3[nm][(k % 10) * OUT + o];
}

__global__ void pack_kernel(
    const float* mW1, const float* mb1, const float* mW2, const float* mb2,
    const float* mW3, const float* mb3,
    const float* dW1, const float* db1, const float* dW2, const float* db2,
    const float* dW3, const float* db3,
    const float* oW1, const float* ob1, const float* oW2, const float* ob2,
    const float* oW3, const float* ob3)
{
    const float* W1[3] = {mW1, dW1, oW1};
    const float* B1[3] = {mb1, db1, ob1};
    const float* W2[3] = {mW2, dW2, oW2};
    const float* B2[3] = {mb2, db2, ob2};
    const float* W3[3] = {mW3, dW3, oW3};
    const float* B3[3] = {mb3, db3, ob3};
    int t = threadIdx.x;

    for (int idx = t; idx < 256; idx += blockDim.x) {      // b1f
        int nt = idx / 32, l = idx % 32;
        int g = l / 4, tg = l % 4;
        int n = 8 * nt + g, k0 = 2 * tg;
        g_tab.b1f[nt][l] = make_uint2(
            packh2(b1val(W1, B1, k0, n), b1val(W1, B1, k0 + 1, n)), 0u);
    }
    for (int idx = t; idx < 512; idx += blockDim.x) {      // b2f
        int nt = idx / 128, r = idx % 128, kc = r / 32, l = r % 32;
        int g = l / 4, tg = l % 4;
        int k0 = 16 * kc + 2 * tg, n = 8 * nt + g;
        g_tab.b2f[nt][kc][l] = make_uint2(
            packh2(b2val(W2, k0, n),     b2val(W2, k0 + 1, n)),
            packh2(b2val(W2, k0 + 8, n), b2val(W2, k0 + 9, n)));
    }
    for (int idx = t; idx < 128; idx += blockDim.x) {      // b3f
        int nt2 = idx / 64, r = idx % 64, kc2 = r / 32, l = r % 32;
        int g = l / 4, tg = l % 4;
        int k0 = 16 * kc2 + 2 * tg, n = 8 * nt2 + g;
        g_tab.b3f[nt2][kc2][l] = make_uint2(
            packh2(b3val(W3, k0, n),     b3val(W3, k0 + 1, n)),
            packh2(b3val(W3, k0 + 8, n), b3val(W3, k0 + 9, n)));
    }
    for (int n = t; n < 32; n += blockDim.x)
        g_tab.b2p[n] = (n < 30) ? B2[n / 10][n % 10] : 0.0f;
    for (int n = t; n < 16; n += blockDim.x) {
        float v = 0.0f;
        if (n < 14) {
            int nm = (n < 4) ? 0 : (n < 8) ? 1 : 2;
            int o = n - ((nm == 0) ? 0 : (nm == 1) ? 4 : 8);
            v = B3[nm][o];
        }
        g_tab.b3p[n] = v;
    }
}

// ---------------------------------------------------------------------------
__device__ __forceinline__ void mma16816(float* d, const unsigned* a,
                                         const uint2 b, const float* c)
{
    asm volatile(
        "mma.sync.aligned.m16n8k16.row.col.f32.f16.f16.f32 "
        "{%0,%1,%2,%3}, {%4,%5,%6,%7}, {%8,%9}, {%10,%11,%12,%13};"
        : "=f"(d[0]), "=f"(d[1]), "=f"(d[2]), "=f"(d[3])
        : "r"(a[0]), "r"(a[1]), "r"(a[2]), "r"(a[3]),
          "r"(b.x), "r"(b.y),
          "f"(c[0]), "f"(c[1]), "f"(c[2]), "f"(c[3]));
}

__device__ __forceinline__ float softplus_f(float x)
{
    return fmaxf(x, 0.0f) + __logf(1.0f + __expf(-fabsf(x)));
}

#define SMEM_STRIDE 20   // 80B rows: 16B-aligned float4 param loads

// ---------------------------------------------------------------------------
__global__ void __launch_bounds__(NTHREADS, 5)
vi_kernel(const float* __restrict__ y, const float* __restrict__ zs, int N,
          float* __restrict__ out)
{
    __shared__ Tab s_tab;
    __shared__ __align__(16) float smemF[NTHREADS * SMEM_STRIDE];
    __shared__ float wsum[NTHREADS / 32];
    __shared__ int sh_last;

    int tid = threadIdx.x;
    {
        const uint4* src = (const uint4*)&g_tab;
        uint4* dst = (uint4*)&s_tab;
        for (int i = tid; i < (int)TAB_U4; i += NTHREADS)
            dst[i] = __ldg(&src[i]);
    }
    __syncthreads();

    int warp = tid / 32, lane = tid % 32;
    int g = lane / 4, tg = lane % 4;
    int blockRow = blockIdx.x * NTHREADS;
    const float2* y2 = (const float2*)y;

    // ---------------- MLP phase: two m16 tiles per warp ----------------
#pragma unroll
    for (int t = 0; t < 2; t++) {
        int tileRow = blockRow + warp * 32 + t * 16;
        int r0 = tileRow + g;     if (r0 > N - 1) r0 = N - 1;
        int r1 = tileRow + g + 8; if (r1 > N - 1) r1 = N - 1;
        float2 yA = __ldg(&y2[r0]);
        float2 yB = __ldg(&y2[r1]);

        unsigned ya[4];
        ya[0] = (tg == 0) ? packh2(yA.x, yA.y) : (tg == 1) ? 0x00003C00u : 0u;
        ya[1] = (tg == 0) ? packh2(yB.x, yB.y) : (tg == 1) ? 0x00003C00u : 0u;
        ya[2] = 0u;
        ya[3] = 0u;

        unsigned a[4][4];
#pragma unroll
        for (int kc = 0; kc < 4; kc++) {
            float d0[4] = {0.f, 0.f, 0.f, 0.f};
            float d1[4] = {0.f, 0.f, 0.f, 0.f};
            mma16816(d0, ya, s_tab.b1f[2 * kc][lane], d0);
            mma16816(d1, ya, s_tab.b1f[2 * kc + 1][lane], d1);
            a[kc][0] = packh2(fmaxf(d0[0], 0.f), fmaxf(d0[1], 0.f));
            a[kc][1] = packh2(fmaxf(d0[2], 0.f), fmaxf(d0[3], 0.f));
            a[kc][2] = packh2(fmaxf(d1[0], 0.f), fmaxf(d1[1], 0.f));
            a[kc][3] = packh2(fmaxf(d1[2], 0.f), fmaxf(d1[3], 0.f));
        }

        float h2[16];
#pragma unroll
        for (int nt = 0; nt < 4; nt++) {
            float c0b = s_tab.b2p[8 * nt + 2 * tg];
            float c1b = s_tab.b2p[8 * nt + 2 * tg + 1];
            float d[4] = {c0b, c1b, c0b, c1b};
#pragma unroll
            for (int kc = 0; kc < 4; kc++)
                mma16816(d, a[kc], s_tab.b2f[nt][kc][lane], d);
            h2[4 * nt + 0] = fmaxf(d[0], 0.0f);
            h2[4 * nt + 1] = fmaxf(d[1], 0.0f);
            h2[4 * nt + 2] = fmaxf(d[2], 0.0f);
            h2[4 * nt + 3] = fmaxf(d[3], 0.0f);
        }

        unsigned a2[2][4];
        a2[0][0] = packh2(h2[0],  h2[1]);
        a2[0][1] = packh2(h2[2],  h2[3]);
        a2[0][2] = packh2(h2[4],  h2[5]);
        a2[0][3] = packh2(h2[6],  h2[7]);
        a2[1][0] = packh2(h2[8],  h2[9]);
        a2[1][1] = packh2(h2[10], h2[11]);
        a2[1][2] = packh2(h2[12], h2[13]);
        a2[1][3] = packh2(h2[14], h2[15]);

#pragma unroll
        for (int nt2 = 0; nt2 < 2; nt2++) {
            float c0b = s_tab.b3p[8 * nt2 + 2 * tg];
            float c1b = s_tab.b3p[8 * nt2 + 2 * tg + 1];
            float d[4] = {c0b, c1b, c0b, c1b};
#pragma unroll
            for (int kc2 = 0; kc2 < 2; kc2++)
                mma16816(d, a2[kc2], s_tab.b3f[nt2][kc2][lane], d);
            int lr0 = warp * 32 + t * 16 + g;
            int lr1 = lr0 + 8;
            int n0 = 8 * nt2 + 2 * tg;
            smemF[lr0 * SMEM_STRIDE + n0]     = d[0];
            smemF[lr0 * SMEM_STRIDE + n0 + 1] = d[1];
            smemF[lr1 * SMEM_STRIDE + n0]     = d[2];
            smemF[lr1 * SMEM_STRIDE + n0 + 1] = d[3];
        }
    }
    __syncwarp();   // MLP results for this warp's 32 rows are in smemF

    // ---------------- entropy prep: thread t owns row t ----------------
    int n = blockRow + tid;
    float val = 0.0f;
    if (n < N) {
        float* f = &smemF[tid * SMEM_STRIDE];
        float4 ldv = *(float4*)&f[4];
        float d0 = softplus_f(ldv.x);
        float d1 = softplus_f(ldv.y);
        float d2 = softplus_f(ldv.z);
        float d3 = softplus_f(ldv.w);
        *(float4*)&f[4] = make_float4(d0, d1, d2, d3);   // write back softplus'd
        float2 yv = __ldg(&y2[n]);
        f[14] = yv.x * 100.0f;                            // yx100
        f[15] = yv.y * 100.0f;                            // yy100
        val = C_PER_SAMPLE + C_ENTROPY + __logf(d0 * d1 * d2 * d3);
    }
    __syncwarp();

    // -------- sample phase: (row,p)-parallel lanes, coalesced zs --------
    // lane l, iter i -> row = warpBase + 4i + l/8, p = l%8.
    // zs float4 index = warpBase*8 + 32i + l : fully contiguous (4 wavefronts).
    {
        int warpBase = blockRow + warp * 32;
        const float4* zp4 = (const float4*)zs + (size_t)warpBase * 8;
        int lr = lane >> 3;
        float acc = 0.0f;
#pragma unroll
        for (int i = 0; i < 8; i++) {
            int rl = 4 * i + lr;
            if (warpBase + rl < N) {
                float4 z = __ldg(&zp4[32 * i + lane]);
                const float* f = &smemF[(warp * 32 + rl) * SMEM_STRIDE];
                float4 mu = *(const float4*)&f[0];
                float4 dd = *(const float4*)&f[4];
                float4 oo = *(const float4*)&f[8];
                float4 ox = *(const float4*)&f[12];   // o4,o5,yx100,yy100

                float xi0 = fmaf(dd.x, z.x, mu.x);
                float xi1 = fmaf(dd.y, z.y, fmaf(oo.x, z.x, mu.y));
                float xi2 = fmaf(dd.z, z.z, fmaf(oo.z, z.y, fmaf(oo.y, z.x, mu.z)));
                float xi3 = fmaf(dd.w, z.w, fmaf(ox.y, z.z,
                              fmaf(ox.x, z.y, fmaf(oo.w, z.x, mu.w))));

                float a2a = xi1 + xi2;
                float a3a = a2a + xi3;
                float s1, c1, s2, c2, s3, c3;
                __sincosf(xi1, &s1, &c1);
                __sincosf(a2a, &s2, &c2);
                __sincosf(a3a, &s3, &c3);

                float px = fmaf(0.5f, c1, fmaf(0.5f, c2, c3));
                float py = xi0 + fmaf(0.5f, s1, fmaf(0.5f, s2, s3));

                float rx = fmaf(-100.0f, px, ox.z);
                float ry = fmaf(-100.0f, py, ox.w);

                float s123 = fmaf(xi1, xi1, fmaf(xi2, xi2, xi3 * xi3));
                float tq = fmaf(xi0 * -8.0f, xi0, -2.0f * s123);
                float r2 = fmaf(rx, rx, ry * ry);
                acc += fmaf(-0.5f, r2, tq);
            }
        }
        val = fmaf(acc, 0.125f, val);   // sum over threads == sum over rows
    }

    // ---- deterministic block reduction ----
#pragma unroll
    for (int o = 16; o > 0; o >>= 1)
        val += __shfl_down_sync(0xffffffffu, val, o);
    if ((tid & 31) == 0) wsum[tid >> 5] = val;
    __syncthreads();
    if (tid == 0) {
        double s = 0.0;
#pragma unroll
        for (int w = 0; w < NTHREADS / 32; w++) s += (double)wsum[w];
        g_partial[blockIdx.x] = s;
        __threadfence();
        unsigned t = atomicAdd(&g_ticket, 1u);
        sh_last = (t == gridDim.x - 1) ? 1 : 0;
    }
    __syncthreads();

    if (sh_last) {
        __threadfence();
        double s = 0.0;
        for (int i = tid; i < (int)gridDim.x; i += NTHREADS)
            s += __ldcg(&g_partial[i]);
        double* sred = (double*)smemF;    // 16B-aligned, plenty of space
        sred[tid] = s;
        __syncthreads();
#pragma unroll
        for (int st = NTHREADS / 2; st > 0; st >>= 1) {
            if (tid < st) sred[tid] += sred[tid + st];
            __syncthreads();
        }
        if (tid == 0) {
            out[0] = (float)(sred[0] / (double)N);
            __threadfence();
            g_ticket = 0;
        }
    }
}

// ---------------------------------------------------------------------------
extern "C" void kernel_launch(void* const* d_in, const int* in_sizes, int n_in,
                              void* d_out, int out_size)
{
    const float* y  = (const float*)d_in[0];
    const float* zs = (const float*)d_in[1];
    int N = in_sizes[0] / 2;
    int nblocks = (N + NTHREADS - 1) / NTHREADS;
    if (nblocks > MAX_BLOCKS) nblocks = MAX_BLOCKS;

    pack_kernel<<<1, 128>>>(
        (const float*)d_in[2],  (const float*)d_in[3],  (const float*)d_in[4],
        (const float*)d_in[5],  (const float*)d_in[6],  (const float*)d_in[7],
        (const float*)d_in[8],  (const float*)d_in[9],  (const float*)d_in[10],
        (const float*)d_in[11], (const float*)d_in[12], (const float*)d_in[13],
        (const float*)d_in[14], (const float*)d_in[15], (const float*)d_in[16],
        (const float*)d_in[17], (const float*)d_in[18], (const float*)d_in[19]);

    vi_kernel<<<nblocks, NTHREADS>>>(y, zs, N, (float*)d_out);
}